// round 8
// baseline (speedup 1.0000x reference)
#include <cuda_runtime.h>
#include <math.h>
#include <float.h>
#include <stdint.h>

// Problem constants (fixed by the reference)
#define B_IMG  32
#define D_DIM  256
#define HW_SZ  4096     // H*W = 64*64
#define K_CB   512
#define NCLS   10
#define NSHR   10

// Tiling: 1024-thread CTA, thread = (pixel = tid&255, group = tid>>8)
#define TP     256      // pixels per block
#define NTHR   1024
#define NGRP   4        // code groups
#define CPG    14       // usable codes per group (4*14 = 56 >= 51)
#define KTP    64       // cbT row stride: groups at 16-col boundaries

#define F32_INF __int_as_float(0x7f800000)

struct ClassRanges { int lo[NCLS]; int cnt[NCLS]; };

typedef unsigned long long ull;

// ---- packed f32x2 helpers (Blackwell): exact per-lane IEEE fp32 semantics --
__device__ __forceinline__ ull pack2(float x) {
    unsigned int b = __float_as_uint(x);
    ull r;
    asm("mov.b64 %0, {%1, %1};" : "=l"(r) : "r"(b));
    return r;
}
__device__ __forceinline__ void fma2(ull& d, ull a, ull b) {
    asm("fma.rn.f32x2 %0, %1, %2, %0;" : "+l"(d) : "l"(a), "l"(b));
}
__device__ __forceinline__ float2 unpack2(ull v) {
    unsigned int lo, hi;
    asm("mov.b64 {%0, %1}, %2;" : "=r"(lo), "=r"(hi) : "l"(v));
    return make_float2(__uint_as_float(lo), __uint_as_float(hi));
}

// ----------------------------------------------------------------------------
// One block: image b, 256 contiguous pixels, 1024 threads (32 warps).
// Thread (p, g) owns pixel p and codes [14g, 14g+13] (7 packed pairs).
// Candidate codes = contiguous codebook slice [lo, lo+cnt) for the image's
// class, TRANSPOSED in smem: cbT[d][col], col = 16*(kk/14) + kk%14
// (pad cols zero, their cb_sqr = +inf).
//
// Main loop is barrier-free: x via coalesced scalar LDG (lane = pixel),
// codes via broadcast LDS.128. Only 7 FFMA2 per thread per d -> fma-pipe
// bound at 8 warps/SMSP.
//
// Bit-exact replication of the reference fp32 arithmetic (validated R2/R6):
//   A   = in_sqr  : sequential ascending sum of fl(x_d*x_d)  (mul then add)
//   g_k = x . c_k : sequential ascending fused-FMA chain (one register lane)
//   d_k = fl( fl(A + p_k) - 2*g_k );  argmin, first-min tie-break
//   (storage col monotone in code index -> col-ascending scan == k-ascending)
// ----------------------------------------------------------------------------
__global__ void __launch_bounds__(NTHR, 1)
vq_kernel(const float* __restrict__ z, const float* __restrict__ cb,
          const int* __restrict__ labels, float* __restrict__ out,
          ClassRanges cr)
{
    extern __shared__ float smem[];
    float* cbT_s = smem;                      // [256 d][KTP]
    float* p_s   = cbT_s + D_DIM * KTP;       // [KTP] cb_sqr by col (+inf pads)
    float* A_s   = p_s + KTP;                 // [256] in_sqr per pixel
    float* rs    = A_s + 256;                 // [NGRP][256] best distance
    int*   ri    = (int*)(rs + NGRP * 256);   // [NGRP][256] storage cols
    int*   best  = (int*)(ri + NGRP * 256);   // [256]

    const int tid = threadIdx.x;
    const int tx  = tid & 31;
    const int wid = tid >> 5;                 // warp 0..31
    const int px  = tid & 255;                // owned pixel
    const int grp = tid >> 8;                 // code group 0..3
    const int b   = blockIdx.y;
    const int hw0 = blockIdx.x * TP;

    const int label = labels[b];
    const int lo    = cr.lo[label];
    const int cnt   = cr.cnt[label];          // 50 or 51

    // ---- init p_s to +inf, zero cbT (covers pad columns) ----
    if (tid < KTP) p_s[tid] = F32_INF;
    for (int i = tid; i < D_DIM * (KTP / 4); i += NTHR)
        *(float4*)&cbT_s[i << 2] = make_float4(0.f, 0.f, 0.f, 0.f);
    __syncthreads();

    // ---- build transposed codebook: cbT[d][col] = cb[lo+kk][d] ----
    for (int i = tid; i < 56 * (D_DIM / 4); i += NTHR) {
        const int kk  = i % 56;               // compact code index
        const int d4  = (i / 56) << 2;
        const int col = ((kk / CPG) << 4) + (kk % CPG);
        if (kk < cnt) {
            const float4 v = *(const float4*)(cb + (size_t)(lo + kk) * D_DIM + d4);
            cbT_s[(d4 + 0) * KTP + col] = v.x;
            cbT_s[(d4 + 1) * KTP + col] = v.y;
            cbT_s[(d4 + 2) * KTP + col] = v.z;
            cbT_s[(d4 + 3) * KTP + col] = v.w;
        }
    }

    // ---- cb_sqr per code from GLOBAL cb (coalesced); warps 0..7 cover 56 ----
    {
        const int kk = wid * 7 % 224;         // warp w -> codes 7w (w<8 useful)
        #pragma unroll
        for (int j = 0; j < 7; ++j) {
            const int k2 = wid * 7 + j;
            if (k2 < cnt) {
                const float* crow = cb + (size_t)(lo + k2) * D_DIM;
                float s = 0.0f;
                #pragma unroll
                for (int d = tx; d < D_DIM; d += 32) {
                    const float v = __ldg(crow + d);
                    s = __fadd_rn(s, __fmul_rn(v, v));
                }
                #pragma unroll
                for (int o = 16; o > 0; o >>= 1)
                    s = __fadd_rn(s, __shfl_xor_sync(0xffffffffu, s, o));
                if (tx == 0) {
                    const int col = ((k2 / CPG) << 4) + (k2 % CPG);
                    p_s[col] = s;
                }
            }
        }
        (void)kk;
    }
    __syncthreads();

    // ---- main loop: barrier-free; 7 FFMA2 + 3.5 LDS + 1 LDG per thread/d ----
    ull acc[7];
    #pragma unroll
    for (int j = 0; j < 7; ++j) acc[j] = 0ULL;
    float Aacc = 0.0f;                        // in_sqr (group 0 only)

    const float* xptr = z + (size_t)b * D_DIM * HW_SZ + hw0 + px;
    const int colbase = grp << 4;
    const bool grp0 = (grp == 0);             // warp-uniform

    #pragma unroll 4
    for (int d = 0; d < D_DIM; ++d) {
        const float xv = __ldg(xptr + (size_t)d * HW_SZ);

        const float* crow = cbT_s + d * KTP + colbase;
        const float4 ca  = *(const float4*)(crow + 0);
        const float4 cbv = *(const float4*)(crow + 4);
        const float4 cc  = *(const float4*)(crow + 8);
        const float2 cd  = *(const float2*)(crow + 12);

        if (grp0)                              // bit-exact ascending-d chain
            Aacc = __fadd_rn(Aacc, __fmul_rn(xv, xv));

        const ull xd = pack2(xv);
        fma2(acc[0], xd, *(const ull*)&ca.x);
        fma2(acc[1], xd, *(const ull*)&ca.z);
        fma2(acc[2], xd, *(const ull*)&cbv.x);
        fma2(acc[3], xd, *(const ull*)&cbv.z);
        fma2(acc[4], xd, *(const ull*)&cc.x);
        fma2(acc[5], xd, *(const ull*)&cc.z);
        fma2(acc[6], xd, *(const ull*)&cd.x);
    }

    if (grp0) A_s[px] = Aacc;
    __syncthreads();

    // ---- distances d = fl(fl(A + p) - 2g); per-thread first-min argmin ----
    {
        const float Av = A_s[px];
        float bd = F32_INF;
        int   bi = colbase;
        #pragma unroll
        for (int j = 0; j < 7; ++j) {
            const int c0i = colbase + (j << 1);
            const float2 g = unpack2(acc[j]);
            const float d0 = __fadd_rn(__fadd_rn(Av, p_s[c0i]), -(2.0f * g.x));
            const float d1 = __fadd_rn(__fadd_rn(Av, p_s[c0i + 1]), -(2.0f * g.y));
            if (d0 < bd) { bd = d0; bi = c0i; }      // strict <: lowest col wins
            if (d1 < bd) { bd = d1; bi = c0i + 1; }
        }
        rs[grp * 256 + px] = bd;
        ri[grp * 256 + px] = bi;
    }
    __syncthreads();

    if (tid < 256) {
        float bd = rs[tid];
        int   bi = ri[tid];
        #pragma unroll
        for (int t2 = 1; t2 < NGRP; ++t2) {
            const float s = rs[t2 * 256 + tid];
            if (s < bd) { bd = s; bi = ri[t2 * 256 + tid]; } // col ascends w/ grp
        }
        best[tid] = bi;
    }
    __syncthreads();

    // ---- epilogue: z_q_x = fl(x + fl(codes - x)), z_q_x_bar = codes ----
    const size_t obase = (size_t)b * D_DIM * HW_SZ + hw0;
    const float* zsrc  = z + obase;
    float* o0 = out + obase;
    float* o1 = out + (size_t)B_IMG * D_DIM * HW_SZ + obase;

    const int ep0 = (tid & 63) << 2;          // 4 pixels
    const int ed0 = tid >> 6;                 // d phase (0..15)
    const int b0 = best[ep0 + 0];
    const int b1 = best[ep0 + 1];
    const int b2 = best[ep0 + 2];
    const int b3 = best[ep0 + 3];

    #pragma unroll 4
    for (int d = ed0; d < D_DIM; d += 16) {
        const size_t off = (size_t)d * HW_SZ + ep0;
        const float* crow = cbT_s + (size_t)d * KTP;
        const float4 xv = *(const float4*)(zsrc + off);
        float4 cv;
        cv.x = crow[b0]; cv.y = crow[b1]; cv.z = crow[b2]; cv.w = crow[b3];
        float4 q;
        q.x = __fadd_rn(xv.x, __fadd_rn(cv.x, -xv.x));
        q.y = __fadd_rn(xv.y, __fadd_rn(cv.y, -xv.y));
        q.z = __fadd_rn(xv.z, __fadd_rn(cv.z, -xv.z));
        q.w = __fadd_rn(xv.w, __fadd_rn(cv.w, -xv.w));
        *(float4*)(o0 + off) = q;
        *(float4*)(o1 + off) = cv;
    }
}

extern "C" void kernel_launch(void* const* d_in, const int* in_sizes, int n_in,
                              void* d_out, int out_size)
{
    const float* z      = (const float*)d_in[0];
    const float* cb     = (const float*)d_in[1];
    const int*   labels = (const int*)d_in[2];
    float*       out    = (float*)d_out;
    (void)in_sizes; (void)n_in; (void)out_size;

    // Class -> contiguous codebook range, replicating
    // round(linspace(-0.5, NCLS-0.51, K-NSHR)) exactly (double + half-even).
    ClassRanges cr;
    for (int c = 0; c < NCLS; ++c) { cr.lo[c] = 0; cr.cnt[c] = 0; }
    const double step = (((double)NCLS - 0.51) + 0.5) / (double)(K_CB - NSHR - 1);
    int prev = -1;
    for (int i = 0; i < K_CB - NSHR; ++i) {
        const double v = -0.5 + (double)i * step;
        int c = (int)nearbyint(v);
        if (c < 0) c = 0;
        if (c > NCLS - 1) c = NCLS - 1;
        if (c != prev) { cr.lo[c] = i; prev = c; }
        cr.cnt[c] += 1;
    }

    const size_t smem_bytes =
        (size_t)(D_DIM * KTP + KTP + 256 + NGRP * 256   // cbT, p, A, rs
                 + NGRP * 256 + 256) * sizeof(float);   // ri, best
    cudaFuncSetAttribute(vq_kernel,
                         cudaFuncAttributeMaxDynamicSharedMemorySize,
                         (int)smem_bytes);

    dim3 grid(HW_SZ / TP, B_IMG);
    vq_kernel<<<grid, NTHR, smem_bytes>>>(z, cb, labels, out, cr);
}

// round 9
// speedup vs baseline: 1.5790x; 1.5790x over previous
#include <cuda_runtime.h>
#include <math.h>
#include <float.h>
#include <stdint.h>

// Problem constants (fixed by the reference)
#define B_IMG  32
#define D_DIM  256
#define HW_SZ  4096     // H*W = 64*64
#define K_CB   512
#define NCLS   10
#define NSHR   10

// Tiling: 512-thread CTA; thread = (pixel pair 2*(tid&127), group tid>>7)
#define TP     256      // pixels per block
#define NTHR   512
#define NGRP   4        // code groups
#define CPG    14       // usable codes per group (4*14 = 56 >= 51)
#define KTP    64       // cbT row stride: groups at 16-col boundaries
#define CHROWS 16       // d-rows staged per chunk
#define NCHNK  (D_DIM / CHROWS)

#define F32_INF __int_as_float(0x7f800000)

struct ClassRanges { int lo[NCLS]; int cnt[NCLS]; };

typedef unsigned long long ull;

// ---- packed f32x2 helpers (Blackwell): exact per-lane IEEE fp32 semantics --
__device__ __forceinline__ ull pack2(float x) {
    unsigned int b = __float_as_uint(x);
    ull r;
    asm("mov.b64 %0, {%1, %1};" : "=l"(r) : "r"(b));
    return r;
}
__device__ __forceinline__ void fma2(ull& d, ull a, ull b) {
    asm("fma.rn.f32x2 %0, %1, %2, %0;" : "+l"(d) : "l"(a), "l"(b));
}
__device__ __forceinline__ ull mul2(ull a, ull b) {
    ull r;
    asm("mul.rn.f32x2 %0, %1, %2;" : "=l"(r) : "l"(a), "l"(b));
    return r;
}
__device__ __forceinline__ void add2(ull& d, ull a) {
    asm("add.rn.f32x2 %0, %0, %1;" : "+l"(d) : "l"(a));
}
__device__ __forceinline__ float2 unpack2(ull v) {
    unsigned int lo, hi;
    asm("mov.b64 {%0, %1}, %2;" : "=r"(lo), "=r"(hi) : "l"(v));
    return make_float2(__uint_as_float(lo), __uint_as_float(hi));
}

// ----------------------------------------------------------------------------
// One block: image b, 256 contiguous pixels, 512 threads (16 warps).
// Thread (pp, g) owns pixels {2pp, 2pp+1} and codes [14g, 14g+13] (7 pairs).
// Codebook slice [lo, lo+cnt) TRANSPOSED in smem: cbT[d][col],
// col = 16*(kk/14) + kk%14 (pad cols zero, cb_sqr = +inf).
// x staged through smem in 16-row chunks (shared by all groups).
//
// Bit-exact replication of the reference fp32 arithmetic (validated R2/R6):
//   A   = in_sqr  : sequential ascending sum of fl(x_d*x_d)  (mul then add)
//   g_k = x . c_k : sequential ascending fused-FMA chain (one register lane)
//   d_k = fl( fl(A + p_k) - 2*g_k );  argmin, first-min tie-break
//   (storage col monotone in code index -> col-ascending scan == k-ascending)
// ----------------------------------------------------------------------------
__global__ void __launch_bounds__(NTHR, 2)
vq_kernel(const float* __restrict__ z, const float* __restrict__ cb,
          const int* __restrict__ labels, float* __restrict__ out,
          ClassRanges cr)
{
    extern __shared__ float smem[];
    float* cbT_s = smem;                      // [256 d][KTP]  (64 KB)
    float* p_s   = cbT_s + D_DIM * KTP;       // [KTP] cb_sqr by col (+inf pads)
    float* A_s   = p_s + KTP;                 // [256] in_sqr per pixel
    float* x_s   = A_s + 256;                 // [CHROWS][256] staged x chunk
    float* rs    = x_s + CHROWS * 256;        // [NGRP][256] best distance
    int*   ri    = (int*)(rs + NGRP * 256);   // [NGRP][256] storage cols
    int*   best  = (int*)(ri + NGRP * 256);   // [256]

    const int tid = threadIdx.x;
    const int tx  = tid & 31;
    const int wid = tid >> 5;                 // warp 0..15
    const int pp  = tid & 127;                // pixel pair id
    const int px0 = pp << 1;                  // first owned pixel
    const int grp = tid >> 7;                 // code group 0..3
    const int b   = blockIdx.y;
    const int hw0 = blockIdx.x * TP;

    const int label = labels[b];
    const int lo    = cr.lo[label];
    const int cnt   = cr.cnt[label];          // 50 or 51

    // ---- init p_s to +inf, zero cbT (covers pad columns) ----
    if (tid < KTP) p_s[tid] = F32_INF;
    for (int i = tid; i < D_DIM * (KTP / 4); i += NTHR)
        *(float4*)&cbT_s[i << 2] = make_float4(0.f, 0.f, 0.f, 0.f);
    __syncthreads();

    // ---- build transposed codebook: cbT[d][col] = cb[lo+kk][d] ----
    for (int i = tid; i < 56 * (D_DIM / 4); i += NTHR) {
        const int kk  = i % 56;               // compact code index
        const int d4  = (i / 56) << 2;
        const int col = ((kk / CPG) << 4) + (kk % CPG);
        if (kk < cnt) {
            const float4 v = *(const float4*)(cb + (size_t)(lo + kk) * D_DIM + d4);
            cbT_s[(d4 + 0) * KTP + col] = v.x;
            cbT_s[(d4 + 1) * KTP + col] = v.y;
            cbT_s[(d4 + 2) * KTP + col] = v.z;
            cbT_s[(d4 + 3) * KTP + col] = v.w;
        }
    }

    // ---- cb_sqr per code from GLOBAL cb (coalesced); warps 0..7 cover 56 ----
    if (wid < 8) {
        #pragma unroll
        for (int j = 0; j < 7; ++j) {
            const int kk = wid * 7 + j;       // 0..55
            if (kk < cnt) {
                const float* crow = cb + (size_t)(lo + kk) * D_DIM;
                float s = 0.0f;
                #pragma unroll
                for (int d = tx; d < D_DIM; d += 32) {
                    const float v = __ldg(crow + d);
                    s = __fadd_rn(s, __fmul_rn(v, v));
                }
                #pragma unroll
                for (int o = 16; o > 0; o >>= 1)
                    s = __fadd_rn(s, __shfl_xor_sync(0xffffffffu, s, o));
                if (tx == 0) {
                    const int col = ((kk / CPG) << 4) + (kk % CPG);
                    p_s[col] = s;
                }
            }
        }
    }
    __syncthreads();

    // ---- main pass: 16 chunks of 16 d-rows staged through smem ----
    ull acc[7][2];                            // 7 code-pairs x 2 pixels
    #pragma unroll
    for (int j = 0; j < 7; ++j) { acc[j][0] = 0ULL; acc[j][1] = 0ULL; }
    ull asq = 0ULL;                           // in_sqr pair (group 0 only)

    const float* xbase = z + (size_t)b * D_DIM * HW_SZ + hw0;
    const int colbase = grp << 4;
    const bool grp0 = (grp == 0);             // warp-uniform

    for (int ch = 0; ch < NCHNK; ++ch) {
        const int dc0 = ch * CHROWS;
        const float* xs = xbase + (size_t)dc0 * HW_SZ;
        __syncthreads();                      // protect x_s reuse
        // stage x chunk [16 d][256 px] (float4, coalesced; 2 per thread)
        #pragma unroll
        for (int g = 0; g < 2; ++g) {
            const int idx = g * NTHR + tid;   // float4 index (0..1023)
            const int row = idx >> 6;
            const int c4  = (idx & 63) << 2;
            *(float4*)&x_s[(row << 8) + c4] =
                *(const float4*)(xs + (size_t)row * HW_SZ + c4);
        }
        __syncthreads();

        #pragma unroll 2
        for (int dd = 0; dd < CHROWS; ++dd) {
            const ull xp = *(const ull*)&x_s[(dd << 8) + px0];  // LDS.64 pair

            const float* crow = cbT_s + (dc0 + dd) * KTP + colbase;
            const float4 ca  = *(const float4*)(crow + 0);
            const float4 cbv = *(const float4*)(crow + 4);
            const float4 cc  = *(const float4*)(crow + 8);
            const float2 cd  = *(const float2*)(crow + 12);

            if (grp0)                          // bit-exact per-pixel chains
                add2(asq, mul2(xp, xp));

            const float2 xv = unpack2(xp);
            const ull xd0 = pack2(xv.x);
            const ull xd1 = pack2(xv.y);

            fma2(acc[0][0], xd0, *(const ull*)&ca.x);
            fma2(acc[0][1], xd1, *(const ull*)&ca.x);
            fma2(acc[1][0], xd0, *(const ull*)&ca.z);
            fma2(acc[1][1], xd1, *(const ull*)&ca.z);
            fma2(acc[2][0], xd0, *(const ull*)&cbv.x);
            fma2(acc[2][1], xd1, *(const ull*)&cbv.x);
            fma2(acc[3][0], xd0, *(const ull*)&cbv.z);
            fma2(acc[3][1], xd1, *(const ull*)&cbv.z);
            fma2(acc[4][0], xd0, *(const ull*)&cc.x);
            fma2(acc[4][1], xd1, *(const ull*)&cc.x);
            fma2(acc[5][0], xd0, *(const ull*)&cc.z);
            fma2(acc[5][1], xd1, *(const ull*)&cc.z);
            fma2(acc[6][0], xd0, *(const ull*)&cd.x);
            fma2(acc[6][1], xd1, *(const ull*)&cd.x);
        }
    }

    if (grp0) *(float2*)&A_s[px0] = unpack2(asq);
    __syncthreads();

    // ---- distances d = fl(fl(A + p) - 2g); per-thread first-min argmin ----
    #pragma unroll
    for (int p = 0; p < 2; ++p) {
        const float Av = A_s[px0 + p];
        float bd = F32_INF;
        int   bi = colbase;
        #pragma unroll
        for (int j = 0; j < 7; ++j) {
            const int c0i = colbase + (j << 1);
            const float2 g = unpack2(acc[j][p]);
            const float d0 = __fadd_rn(__fadd_rn(Av, p_s[c0i]), -(2.0f * g.x));
            const float d1 = __fadd_rn(__fadd_rn(Av, p_s[c0i + 1]), -(2.0f * g.y));
            if (d0 < bd) { bd = d0; bi = c0i; }      // strict <: lowest col wins
            if (d1 < bd) { bd = d1; bi = c0i + 1; }
        }
        rs[grp * 256 + px0 + p] = bd;
        ri[grp * 256 + px0 + p] = bi;
    }
    __syncthreads();

    if (tid < 256) {
        float bd = rs[tid];
        int   bi = ri[tid];
        #pragma unroll
        for (int t2 = 1; t2 < NGRP; ++t2) {
            const float s = rs[t2 * 256 + tid];
            if (s < bd) { bd = s; bi = ri[t2 * 256 + tid]; } // col ascends w/ grp
        }
        best[tid] = bi;
    }
    __syncthreads();

    // ---- epilogue: z_q_x = fl(x + fl(codes - x)), z_q_x_bar = codes ----
    const size_t obase = (size_t)b * D_DIM * HW_SZ + hw0;
    const float* zsrc  = z + obase;
    float* o0 = out + obase;
    float* o1 = out + (size_t)B_IMG * D_DIM * HW_SZ + obase;

    const int ep0 = (tid & 127) << 1;         // 2 pixels
    const int ed0 = tid >> 7;                 // d phase (0..3)
    const int b0 = best[ep0 + 0];
    const int b1 = best[ep0 + 1];

    #pragma unroll 4
    for (int d = ed0; d < D_DIM; d += 4) {
        const size_t off = (size_t)d * HW_SZ + ep0;
        const float* crow = cbT_s + (size_t)d * KTP;
        const float2 xv = *(const float2*)(zsrc + off);
        float2 cv;
        cv.x = crow[b0]; cv.y = crow[b1];
        float2 q;
        q.x = __fadd_rn(xv.x, __fadd_rn(cv.x, -xv.x));
        q.y = __fadd_rn(xv.y, __fadd_rn(cv.y, -xv.y));
        *(float2*)(o0 + off) = q;
        *(float2*)(o1 + off) = cv;
    }
}

extern "C" void kernel_launch(void* const* d_in, const int* in_sizes, int n_in,
                              void* d_out, int out_size)
{
    const float* z      = (const float*)d_in[0];
    const float* cb     = (const float*)d_in[1];
    const int*   labels = (const int*)d_in[2];
    float*       out    = (float*)d_out;
    (void)in_sizes; (void)n_in; (void)out_size;

    // Class -> contiguous codebook range, replicating
    // round(linspace(-0.5, NCLS-0.51, K-NSHR)) exactly (double + half-even).
    ClassRanges cr;
    for (int c = 0; c < NCLS; ++c) { cr.lo[c] = 0; cr.cnt[c] = 0; }
    const double step = (((double)NCLS - 0.51) + 0.5) / (double)(K_CB - NSHR - 1);
    int prev = -1;
    for (int i = 0; i < K_CB - NSHR; ++i) {
        const double v = -0.5 + (double)i * step;
        int c = (int)nearbyint(v);
        if (c < 0) c = 0;
        if (c > NCLS - 1) c = NCLS - 1;
        if (c != prev) { cr.lo[c] = i; prev = c; }
        cr.cnt[c] += 1;
    }

    const size_t smem_bytes =
        (size_t)(D_DIM * KTP + KTP + 256 + CHROWS * 256   // cbT, p, A, x
                 + NGRP * 256 + NGRP * 256 + 256) * sizeof(float); // rs, ri, best
    cudaFuncSetAttribute(vq_kernel,
                         cudaFuncAttributeMaxDynamicSharedMemorySize,
                         (int)smem_bytes);

    dim3 grid(HW_SZ / TP, B_IMG);
    vq_kernel<<<grid, NTHR, smem_bytes>>>(z, cb, labels, out, cr);
}

// round 10
// speedup vs baseline: 1.5805x; 1.0009x over previous
#include <cuda_runtime.h>
#include <math.h>
#include <float.h>
#include <stdint.h>

// Problem constants (fixed by the reference)
#define B_IMG  32
#define D_DIM  256
#define HW_SZ  4096     // H*W = 64*64
#define K_CB   512
#define NCLS   10
#define NSHR   10

// Tiling: 512-thread CTA; thread = (pixel pair 2*(tid&127), group tid>>7)
#define TP     256      // pixels per block
#define NTHR   512
#define NGRP   4        // code groups
#define CPG    14       // usable codes per group (4*14 = 56 >= 51)
#define KTP    64       // cbT row stride: groups at 16-col boundaries
#define CHROWS 8        // d-rows per staged chunk
#define NCHNK  (D_DIM / CHROWS)   // 32
#define NBUF   4        // staging ring buffers
#define DIST   2        // prefetch distance (chunks)

#define F32_INF __int_as_float(0x7f800000)

struct ClassRanges { int lo[NCLS]; int cnt[NCLS]; };

typedef unsigned long long ull;

// ---- packed f32x2 helpers (Blackwell): exact per-lane IEEE fp32 semantics --
__device__ __forceinline__ ull pack2(float x) {
    unsigned int b = __float_as_uint(x);
    ull r;
    asm("mov.b64 %0, {%1, %1};" : "=l"(r) : "r"(b));
    return r;
}
__device__ __forceinline__ void fma2(ull& d, ull a, ull b) {
    asm("fma.rn.f32x2 %0, %1, %2, %0;" : "+l"(d) : "l"(a), "l"(b));
}
__device__ __forceinline__ ull mul2(ull a, ull b) {
    ull r;
    asm("mul.rn.f32x2 %0, %1, %2;" : "=l"(r) : "l"(a), "l"(b));
    return r;
}
__device__ __forceinline__ void add2(ull& d, ull a) {
    asm("add.rn.f32x2 %0, %0, %1;" : "+l"(d) : "l"(a));
}
__device__ __forceinline__ float2 unpack2(ull v) {
    unsigned int lo, hi;
    asm("mov.b64 {%0, %1}, %2;" : "=r"(lo), "=r"(hi) : "l"(v));
    return make_float2(__uint_as_float(lo), __uint_as_float(hi));
}

// ---- cp.async helpers ------------------------------------------------------
__device__ __forceinline__ unsigned int smem_u32(const void* p) {
    return (unsigned int)__cvta_generic_to_shared(p);
}
__device__ __forceinline__ void cp16(unsigned int dst, const void* src) {
    asm volatile("cp.async.cg.shared.global [%0], [%1], 16;"
                 :: "r"(dst), "l"(src) : "memory");
}
#define CP_COMMIT()  asm volatile("cp.async.commit_group;" ::: "memory")
#define CP_WAIT(n)   asm volatile("cp.async.wait_group %0;" :: "n"(n) : "memory")

// ----------------------------------------------------------------------------
// One block: image b, 256 contiguous pixels, 512 threads (16 warps).
// Thread (pp, g) owns pixels {2pp, 2pp+1} and codes [14g, 14g+13] (7 pairs).
// Codebook slice [lo, lo+cnt) TRANSPOSED in smem: cbT[d][col],
// col = 16*(kk/14) + kk%14 (pad cols zero, cb_sqr = +inf).
//
// x is staged through a 4-buffer cp.async ring, prefetch distance 2, ONE
// __syncthreads per chunk. Safety: at iter ch the writer targets buf
// (ch+2)%4; the oldest possible reader (skew <= 1 iter, enforced by the
// per-iter barrier) holds buf (ch-1)%4 or (ch)%4 — disjoint. All
// compute(ch-2) precede barrier(ch-1), which precedes any issue(ch+2).
// An (empty) commit_group is executed EVERY iter so wait_group 2 always
// retires chunk ch (groups complete in order).
//
// Bit-exact replication of the reference fp32 arithmetic (validated R2/R6/R9):
//   A   = in_sqr  : sequential ascending sum of fl(x_d*x_d)  (mul then add)
//   g_k = x . c_k : sequential ascending fused-FMA chain (one register lane)
//   d_k = fl( fl(A + p_k) - 2*g_k );  argmin, first-min tie-break
//   (storage col monotone in code index -> col-ascending scan == k-ascending)
// ----------------------------------------------------------------------------
__global__ void __launch_bounds__(NTHR, 2)
vq_kernel(const float* __restrict__ z, const float* __restrict__ cb,
          const int* __restrict__ labels, float* __restrict__ out,
          ClassRanges cr)
{
    extern __shared__ float smem[];
    float* cbT_s = smem;                      // [256 d][KTP]  (64 KB)
    float* p_s   = cbT_s + D_DIM * KTP;       // [KTP] cb_sqr by col (+inf pads)
    float* A_s   = p_s + KTP;                 // [256] in_sqr per pixel
    float* xq    = A_s + 256;                 // [NBUF][CHROWS*256] ring (32 KB)
    float* rs    = xq + NBUF * CHROWS * 256;  // [NGRP][256] best distance
    int*   ri    = (int*)(rs + NGRP * 256);   // [NGRP][256] storage cols
    int*   best  = (int*)(ri + NGRP * 256);   // [256]

    const int tid = threadIdx.x;
    const int tx  = tid & 31;
    const int wid = tid >> 5;                 // warp 0..15
    const int pp  = tid & 127;                // pixel pair id
    const int px0 = pp << 1;                  // first owned pixel
    const int grp = tid >> 7;                 // code group 0..3
    const int b   = blockIdx.y;
    const int hw0 = blockIdx.x * TP;

    const int label = labels[b];
    const int lo    = cr.lo[label];
    const int cnt   = cr.cnt[label];          // 50 or 51

    const float* xbase = z + (size_t)b * D_DIM * HW_SZ + hw0;

    // Per-thread staging slot: one float4 per chunk (512 * 16B = 8KB = chunk)
    const int srow = tid >> 6;                // 0..7
    const int sc4  = (tid & 63) << 2;         // 0..252
    const unsigned int my_dst_off =
        (unsigned)((srow << 8) + sc4) * 4u;   // byte offset within a buffer

    // ---- prologue: prefetch chunks 0 and 1 (one group each) ----
    #pragma unroll
    for (int c0 = 0; c0 < DIST; ++c0) {
        cp16(smem_u32(xq + c0 * (CHROWS * 256)) + my_dst_off,
             xbase + (size_t)(c0 * CHROWS + srow) * HW_SZ + sc4);
        CP_COMMIT();
    }

    // ---- init p_s to +inf, zero cbT (covers pad columns) ----
    if (tid < KTP) p_s[tid] = F32_INF;
    for (int i = tid; i < D_DIM * (KTP / 4); i += NTHR)
        *(float4*)&cbT_s[i << 2] = make_float4(0.f, 0.f, 0.f, 0.f);
    __syncthreads();

    // ---- build transposed codebook: cbT[d][col] = cb[lo+kk][d] ----
    for (int i = tid; i < 56 * (D_DIM / 4); i += NTHR) {
        const int kk  = i % 56;               // compact code index
        const int d4  = (i / 56) << 2;
        const int col = ((kk / CPG) << 4) + (kk % CPG);
        if (kk < cnt) {
            const float4 v = *(const float4*)(cb + (size_t)(lo + kk) * D_DIM + d4);
            cbT_s[(d4 + 0) * KTP + col] = v.x;
            cbT_s[(d4 + 1) * KTP + col] = v.y;
            cbT_s[(d4 + 2) * KTP + col] = v.z;
            cbT_s[(d4 + 3) * KTP + col] = v.w;
        }
    }

    // ---- cb_sqr per code from GLOBAL cb (coalesced); warps 0..7 cover 56 ----
    if (wid < 8) {
        #pragma unroll
        for (int j = 0; j < 7; ++j) {
            const int kk = wid * 7 + j;       // 0..55
            if (kk < cnt) {
                const float* crow = cb + (size_t)(lo + kk) * D_DIM;
                float s = 0.0f;
                #pragma unroll
                for (int d = tx; d < D_DIM; d += 32) {
                    const float v = __ldg(crow + d);
                    s = __fadd_rn(s, __fmul_rn(v, v));
                }
                #pragma unroll
                for (int o = 16; o > 0; o >>= 1)
                    s = __fadd_rn(s, __shfl_xor_sync(0xffffffffu, s, o));
                if (tx == 0) {
                    const int col = ((kk / CPG) << 4) + (kk % CPG);
                    p_s[col] = s;
                }
            }
        }
    }
    __syncthreads();

    // ---- main pass: 32 chunks of 8 d-rows through the cp.async ring ----
    ull acc[7][2];                            // 7 code-pairs x 2 pixels
    #pragma unroll
    for (int j = 0; j < 7; ++j) { acc[j][0] = 0ULL; acc[j][1] = 0ULL; }
    ull asq = 0ULL;                           // in_sqr pair (group 0 only)

    const int colbase = grp << 4;
    const bool grp0 = (grp == 0);             // warp-uniform

    for (int ch = 0; ch < NCHNK; ++ch) {
        // prefetch chunk ch+DIST (empty commit in the tail keeps group order)
        if (ch + DIST < NCHNK) {
            cp16(smem_u32(xq + ((ch + DIST) & (NBUF - 1)) * (CHROWS * 256))
                     + my_dst_off,
                 xbase + (size_t)((ch + DIST) * CHROWS + srow) * HW_SZ + sc4);
        }
        CP_COMMIT();
        CP_WAIT(2);                           // retires chunk ch
        __syncthreads();

        const float* cur = xq + (ch & (NBUF - 1)) * (CHROWS * 256);
        const int dc0 = ch * CHROWS;

        #pragma unroll
        for (int dd = 0; dd < CHROWS; ++dd) {
            const ull xp = *(const ull*)&cur[(dd << 8) + px0];  // LDS.64 pair

            const float* crow = cbT_s + (dc0 + dd) * KTP + colbase;
            const float4 ca  = *(const float4*)(crow + 0);
            const float4 cbv = *(const float4*)(crow + 4);
            const float4 cc  = *(const float4*)(crow + 8);
            const float2 cd  = *(const float2*)(crow + 12);

            if (grp0)                          // bit-exact per-pixel chains
                add2(asq, mul2(xp, xp));

            const float2 xv = unpack2(xp);
            const ull xd0 = pack2(xv.x);
            const ull xd1 = pack2(xv.y);

            fma2(acc[0][0], xd0, *(const ull*)&ca.x);
            fma2(acc[0][1], xd1, *(const ull*)&ca.x);
            fma2(acc[1][0], xd0, *(const ull*)&ca.z);
            fma2(acc[1][1], xd1, *(const ull*)&ca.z);
            fma2(acc[2][0], xd0, *(const ull*)&cbv.x);
            fma2(acc[2][1], xd1, *(const ull*)&cbv.x);
            fma2(acc[3][0], xd0, *(const ull*)&cbv.z);
            fma2(acc[3][1], xd1, *(const ull*)&cbv.z);
            fma2(acc[4][0], xd0, *(const ull*)&cc.x);
            fma2(acc[4][1], xd1, *(const ull*)&cc.x);
            fma2(acc[5][0], xd0, *(const ull*)&cc.z);
            fma2(acc[5][1], xd1, *(const ull*)&cc.z);
            fma2(acc[6][0], xd0, *(const ull*)&cd.x);
            fma2(acc[6][1], xd1, *(const ull*)&cd.x);
        }
    }

    if (grp0) *(float2*)&A_s[px0] = unpack2(asq);
    __syncthreads();

    // ---- distances d = fl(fl(A + p) - 2g); per-thread first-min argmin ----
    #pragma unroll
    for (int p = 0; p < 2; ++p) {
        const float Av = A_s[px0 + p];
        float bd = F32_INF;
        int   bi = colbase;
        #pragma unroll
        for (int j = 0; j < 7; ++j) {
            const int c0i = colbase + (j << 1);
            const float2 g = unpack2(acc[j][p]);
            const float d0 = __fadd_rn(__fadd_rn(Av, p_s[c0i]), -(2.0f * g.x));
            const float d1 = __fadd_rn(__fadd_rn(Av, p_s[c0i + 1]), -(2.0f * g.y));
            if (d0 < bd) { bd = d0; bi = c0i; }      // strict <: lowest col wins
            if (d1 < bd) { bd = d1; bi = c0i + 1; }
        }
        rs[grp * 256 + px0 + p] = bd;
        ri[grp * 256 + px0 + p] = bi;
    }
    __syncthreads();

    if (tid < 256) {
        float bd = rs[tid];
        int   bi = ri[tid];
        #pragma unroll
        for (int t2 = 1; t2 < NGRP; ++t2) {
            const float s = rs[t2 * 256 + tid];
            if (s < bd) { bd = s; bi = ri[t2 * 256 + tid]; } // col ascends w/ grp
        }
        best[tid] = bi;
    }
    __syncthreads();

    // ---- epilogue: z_q_x = fl(x + fl(codes - x)), z_q_x_bar = codes ----
    const size_t obase = (size_t)b * D_DIM * HW_SZ + hw0;
    const float* zsrc  = z + obase;
    float* o0 = out + obase;
    float* o1 = out + (size_t)B_IMG * D_DIM * HW_SZ + obase;

    const int ep0 = (tid & 127) << 1;         // 2 pixels
    const int ed0 = tid >> 7;                 // d phase (0..3)
    const int b0 = best[ep0 + 0];
    const int b1 = best[ep0 + 1];

    #pragma unroll 4
    for (int d = ed0; d < D_DIM; d += 4) {
        const size_t off = (size_t)d * HW_SZ + ep0;
        const float* crow = cbT_s + (size_t)d * KTP;
        const float2 xv = *(const float2*)(zsrc + off);
        float2 cv;
        cv.x = crow[b0]; cv.y = crow[b1];
        float2 q;
        q.x = __fadd_rn(xv.x, __fadd_rn(cv.x, -xv.x));
        q.y = __fadd_rn(xv.y, __fadd_rn(cv.y, -xv.y));
        *(float2*)(o0 + off) = q;
        *(float2*)(o1 + off) = cv;
    }
}

extern "C" void kernel_launch(void* const* d_in, const int* in_sizes, int n_in,
                              void* d_out, int out_size)
{
    const float* z      = (const float*)d_in[0];
    const float* cb     = (const float*)d_in[1];
    const int*   labels = (const int*)d_in[2];
    float*       out    = (float*)d_out;
    (void)in_sizes; (void)n_in; (void)out_size;

    // Class -> contiguous codebook range, replicating
    // round(linspace(-0.5, NCLS-0.51, K-NSHR)) exactly (double + half-even).
    ClassRanges cr;
    for (int c = 0; c < NCLS; ++c) { cr.lo[c] = 0; cr.cnt[c] = 0; }
    const double step = (((double)NCLS - 0.51) + 0.5) / (double)(K_CB - NSHR - 1);
    int prev = -1;
    for (int i = 0; i < K_CB - NSHR; ++i) {
        const double v = -0.5 + (double)i * step;
        int c = (int)nearbyint(v);
        if (c < 0) c = 0;
        if (c > NCLS - 1) c = NCLS - 1;
        if (c != prev) { cr.lo[c] = i; prev = c; }
        cr.cnt[c] += 1;
    }

    const size_t smem_bytes =
        (size_t)(D_DIM * KTP + KTP + 256                       // cbT, p, A
                 + NBUF * CHROWS * 256                         // x ring
                 + NGRP * 256 + NGRP * 256 + 256) * sizeof(float); // rs, ri, best
    cudaFuncSetAttribute(vq_kernel,
                         cudaFuncAttributeMaxDynamicSharedMemorySize,
                         (int)smem_bytes);

    dim3 grid(HW_SZ / TP, B_IMG);
    vq_kernel<<<grid, NTHR, smem_bytes>>>(z, cb, labels, out, cr);
}